// round 1
// baseline (speedup 1.0000x reference)
#include <cuda_runtime.h>
#include <cuda_bf16.h>

#define Bn   8
#define Cn   256
#define Gn   32
#define CPG  8           // channels per group = 256/32
#define Hn   56
#define Wn   56
#define HWn  3136        // 56*56
#define QW   14          // float4 quads per row
#define TOTAL_THREADS (Bn*Gn*Hn*QW)   // 200704

__global__ __launch_bounds__(256)
void SKA_20950850470021_kernel(const float* __restrict__ x,
                               const float* __restrict__ w,
                               float* __restrict__ out) {
    int idx = blockIdx.x * blockDim.x + threadIdx.x;
    if (idx >= TOTAL_THREADS) return;

    int q = idx % QW;
    int t = idx / QW;
    int h = t % Hn;
    t /= Hn;
    int g = t % Gn;
    int b = t / Gn;
    int w0 = q * 4;

    // ---- load the 9 weight taps for this (b,g,h,quad) once; reused by 8 channels ----
    const float* wbase = w + ((size_t)(b * Gn + g) * 9) * HWn + (size_t)h * Wn + w0;
    float4 wt[9];
#pragma unroll
    for (int k = 0; k < 9; ++k)
        wt[k] = *reinterpret_cast<const float4*>(wbase + (size_t)k * HWn);

    const bool hasL = (q > 0);
    const bool hasR = (q < QW - 1);

    const size_t base = ((size_t)b * Cn + g) * HWn + (size_t)h * Wn + w0;

#pragma unroll
    for (int i = 0; i < CPG; ++i) {
        const float* xc = x + base + (size_t)i * Gn * HWn;

        // 3 rows x 6 columns (w0-1 .. w0+4) of input, zero-filled at borders
        float v[3][6];
#pragma unroll
        for (int r = 0; r < 3; ++r) {
            int hh = h + r - 1;
            bool hv = (hh >= 0) && (hh < Hn);
            const float* xr = xc + (r - 1) * Wn;
            float4 c = hv ? *reinterpret_cast<const float4*>(xr)
                          : make_float4(0.f, 0.f, 0.f, 0.f);
            v[r][0] = (hv && hasL) ? xr[-1] : 0.f;
            v[r][1] = c.x;
            v[r][2] = c.y;
            v[r][3] = c.z;
            v[r][4] = c.w;
            v[r][5] = (hv && hasR) ? xr[4] : 0.f;
        }

        float4 acc = make_float4(0.f, 0.f, 0.f, 0.f);
#pragma unroll
        for (int r = 0; r < 3; ++r) {
#pragma unroll
            for (int dx = 0; dx < 3; ++dx) {
                const float4 wk = wt[r * 3 + dx];
                acc.x += v[r][0 + dx] * wk.x;
                acc.y += v[r][1 + dx] * wk.y;
                acc.z += v[r][2 + dx] * wk.z;
                acc.w += v[r][3 + dx] * wk.w;
            }
        }

        *reinterpret_cast<float4*>(out + base + (size_t)i * Gn * HWn) = acc;
    }
}

extern "C" void kernel_launch(void* const* d_in, const int* in_sizes, int n_in,
                              void* d_out, int out_size) {
    const float* x = (const float*)d_in[0];   // (8,256,56,56)
    const float* w = (const float*)d_in[1];   // (8,32,9,56,56)
    float* out = (float*)d_out;               // (8,256,56,56)

    const int threads = 256;
    const int blocks = (TOTAL_THREADS + threads - 1) / threads;  // 784
    SKA_20950850470021_kernel<<<blocks, threads>>>(x, w, out);
}

// round 2
// speedup vs baseline: 1.0118x; 1.0118x over previous
#include <cuda_runtime.h>
#include <cuda_bf16.h>

#define Bn   8
#define Cn   256
#define Gn   32
#define Hn   56
#define Wn   56
#define HWn  3136        // 56*56
#define QW   14          // float4 quads per row
#define NPART 4          // channel-pairs per (b,g,h,q)
#define NCH   2          // channels per thread
#define TOTAL_THREADS (Bn*Gn*Hn*QW*NPART)   // 802816

__global__ __launch_bounds__(256, 5)
void SKA_20950850470021_kernel(const float* __restrict__ x,
                               const float* __restrict__ w,
                               float* __restrict__ out) {
    int idx = blockIdx.x * blockDim.x + threadIdx.x;

    int q = idx % QW;
    int t = idx / QW;
    int h = t % Hn;
    t /= Hn;
    int g = t % Gn;
    t /= Gn;
    int b = t % Bn;
    int p = t / Bn;          // 0..3 : which pair of channels

    const int w0 = q * 4;
    const bool hasL = (q > 0);
    const bool hasR = (q < QW - 1);

    // weight base for this (b,g), tap k at +k*HWn
    const float* wbase = w + ((b * Gn + g) * 9) * HWn + h * Wn + w0;

    // x/out base for channel c = (p*2 + j)*32 + g
    const int base = (b * Cn + g) * HWn + h * Wn + w0;
    const int choff0 = (p * NCH + 0) * Gn * HWn;
    const int choff1 = (p * NCH + 1) * Gn * HWn;
    const float* xc0 = x + base + choff0;
    const float* xc1 = x + base + choff1;

    float4 acc0 = make_float4(0.f, 0.f, 0.f, 0.f);
    float4 acc1 = make_float4(0.f, 0.f, 0.f, 0.f);

#pragma unroll
    for (int r = 0; r < 3; ++r) {
        int hh = h + r - 1;
        if (hh < 0 || hh >= Hn) continue;   // skip whole row (weights would hit zeros)

        // 3 weight taps of this row (each a float4 over the 4 output columns)
        const float* wr = wbase + (3 * r) * HWn;
        float4 wk0 = *reinterpret_cast<const float4*>(wr);
        float4 wk1 = *reinterpret_cast<const float4*>(wr + HWn);
        float4 wk2 = *reinterpret_cast<const float4*>(wr + 2 * HWn);

        {   // channel 0 of the pair
            const float* xr = xc0 + (r - 1) * Wn;
            float4 c = *reinterpret_cast<const float4*>(xr);
            float  l = hasL ? xr[-1] : 0.f;
            float  rr = hasR ? xr[4] : 0.f;
            acc0.x += l   * wk0.x + c.x * wk1.x + c.y * wk2.x;
            acc0.y += c.x * wk0.y + c.y * wk1.y + c.z * wk2.y;
            acc0.z += c.y * wk0.z + c.z * wk1.z + c.w * wk2.z;
            acc0.w += c.z * wk0.w + c.w * wk1.w + rr  * wk2.w;
        }
        {   // channel 1 of the pair
            const float* xr = xc1 + (r - 1) * Wn;
            float4 c = *reinterpret_cast<const float4*>(xr);
            float  l = hasL ? xr[-1] : 0.f;
            float  rr = hasR ? xr[4] : 0.f;
            acc1.x += l   * wk0.x + c.x * wk1.x + c.y * wk2.x;
            acc1.y += c.x * wk0.y + c.y * wk1.y + c.z * wk2.y;
            acc1.z += c.y * wk0.z + c.z * wk1.z + c.w * wk2.z;
            acc1.w += c.z * wk0.w + c.w * wk1.w + rr  * wk2.w;
        }
    }

    *reinterpret_cast<float4*>(out + base + choff0) = acc0;
    *reinterpret_cast<float4*>(out + base + choff1) = acc1;
}

extern "C" void kernel_launch(void* const* d_in, const int* in_sizes, int n_in,
                              void* d_out, int out_size) {
    const float* x = (const float*)d_in[0];   // (8,256,56,56)
    const float* w = (const float*)d_in[1];   // (8,32,9,56,56)
    float* out = (float*)d_out;               // (8,256,56,56)

    const int threads = 256;
    const int blocks = TOTAL_THREADS / threads;  // 3136
    SKA_20950850470021_kernel<<<blocks, threads>>>(x, w, out);
}